// round 11
// baseline (speedup 1.0000x reference)
#include <cuda_runtime.h>
#include <cuda_fp16.h>
#include <cstdint>

// ===================== problem constants =====================
#define BATCH_ 8192
#define O_     8
#define K_     2048      // N*U
#define V_     256

// ===================== GEMM tiling =====================
#define BM 128
#define BN 256           // full o per CTA
#define BK 64            // halves per pipeline chunk (128B per row)
#define NSTG 2
#define ROWB 144         // 128B data + 16B pad (conflict-free ldmatrix)
#define A_BYTES (BM * ROWB)            // 18432
#define B_BYTES (BN * ROWB)            // 36864
#define STG_BYTES (A_BYTES + B_BYTES)  // 55296
#define SMEM_TOTAL (NSTG * STG_BYTES)  // 110592

// ===================== scratch =====================
__device__ __half g_xh[(size_t)BATCH_ * K_];   // fp16 X (active n-slices only)
__device__ __half g_wh[(size_t)O_ * V_ * K_];  // gated, transposed fp16 W [o][v][k]

// ===================== helpers =====================
__device__ __forceinline__ uint32_t smem_u32(const void* p) {
    uint32_t a;
    asm("{ .reg .u64 t; cvta.to.shared.u64 t, %1; cvt.u32.u64 %0, t; }" : "=r"(a) : "l"(p));
    return a;
}
__device__ __forceinline__ void cpa16(uint32_t d, const void* g) {
    asm volatile("cp.async.cg.shared.global [%0], [%1], 16;" :: "r"(d), "l"(g));
}
#define CP_COMMIT() asm volatile("cp.async.commit_group;" ::: "memory")
#define CP_WAIT1()  asm volatile("cp.async.wait_group 1;" ::: "memory")

__device__ __forceinline__ void ldsm4(uint32_t (&r)[4], uint32_t addr) {
    asm volatile("ldmatrix.sync.aligned.m8n8.x4.shared.b16 {%0,%1,%2,%3}, [%4];"
                 : "=r"(r[0]), "=r"(r[1]), "=r"(r[2]), "=r"(r[3]) : "r"(addr));
}
__device__ __forceinline__ void mma16816(float* c, const uint32_t* a,
                                         uint32_t b0, uint32_t b1) {
    asm volatile(
        "mma.sync.aligned.m16n8k16.row.col.f32.f16.f16.f32 "
        "{%0,%1,%2,%3}, {%4,%5,%6,%7}, {%8,%9}, {%0,%1,%2,%3};"
        : "+f"(c[0]), "+f"(c[1]), "+f"(c[2]), "+f"(c[3])
        : "r"(a[0]), "r"(a[1]), "r"(a[2]), "r"(a[3]), "r"(b0), "r"(b1));
}

// fast-math gate (identical everywhere -> consistent open/closed decisions)
__device__ __forceinline__ float gate_z(const float* u_param, const float* alpha, int idx) {
    float uu = u_param[idx];
    float s = __logf(uu) - __logf(1.0f - uu) + __logf(alpha[0]) * (1.0f / 0.9f);
    s = 1.0f / (1.0f + __expf(-s));
    float z = s * 1.2f - 0.1f;
    return fminf(fmaxf(z, 0.0f), 1.0f);
}

// ===================== prepass (3072 blocks, 256 threads) =====================
// [0, 2048):    X -> fp16 for active-n slices (4 b-rows per block)
// [2048, 3072): gate-scaled W transpose for open gates
__global__ void prep(const float* __restrict__ X,
                     const float* __restrict__ T,
                     const float* __restrict__ alpha,
                     const float* __restrict__ u_param) {
    __shared__ float zs[64];
    __shared__ int actn[8];
    int tid = threadIdx.x;
    if (tid < 64) zs[tid] = gate_z(u_param, alpha, tid);
    __syncthreads();

    if (blockIdx.x < 2048) {
        if (tid < 8) {
            int a = 0;
#pragma unroll
            for (int o = 0; o < 8; o++) a |= (zs[o * 8 + tid] > 0.0f);
            actn[tid] = a;
        }
        __syncthreads();
        int b  = (blockIdx.x << 2) + (tid >> 6);
        int u4 = tid & 63;
#pragma unroll
        for (int n = 0; n < 8; n++) {
            if (!actn[n]) continue;
            size_t e = ((size_t)b * 8 + n) * 256 + u4 * 4;
            float4 v = *reinterpret_cast<const float4*>(X + e);
            __half2 h0 = __floats2half2_rn(v.x, v.y);
            __half2 h1 = __floats2half2_rn(v.z, v.w);
            uint2 w;
            w.x = *reinterpret_cast<uint32_t*>(&h0);
            w.y = *reinterpret_cast<uint32_t*>(&h1);
            *reinterpret_cast<uint2*>(g_xh + e) = w;
        }
        return;
    }

    // ---- W gate + transpose, open gates only ----
    __shared__ float tile[64][65];
    int blk = blockIdx.x - 2048;   // 0..1023
    int on = blk >> 4;
    int o = on >> 3, n = on & 7;
    int u0 = ((blk >> 2) & 3) * 64;
    int v0 = (blk & 3) * 64;
    float z = zs[o * 8 + n];
    if (z == 0.0f) return;

    const float* tb = T + (((size_t)(o * 8 + n) * 256 + u0) * 256 + v0);
#pragma unroll
    for (int i = 0; i < 16; i++) {
        int r = i * 4 + (tid >> 6);
        int c = tid & 63;
        tile[r][c] = tb[(size_t)r * 256 + c];
    }
    __syncthreads();

    __half* wb = g_wh + ((size_t)o * 256 + v0) * 2048 + n * 256 + u0;
#pragma unroll
    for (int i = 0; i < 16; i++) {
        int r = i * 4 + (tid >> 6);   // v-row
        int c = tid & 63;             // u-col
        wb[(size_t)r * 2048 + c] = __float2half_rn(tile[c][r] * z);
    }
}

// ===================== fp16 pipelined GEMM =====================
// Tile BM=128 x BN=256 (full o). Grid (64, 8): x = m-tile (fast -> contiguous
// bids per o), y = o. 512 threads = 16 warps (4m x 4n), warp tile 32x64.
__global__ __launch_bounds__(512)
void gemm_fp16(const float* __restrict__ alpha,
               const float* __restrict__ u_param,
               float* __restrict__ out) {
    extern __shared__ char smem[];
    const uint32_t sb = smem_u32(smem);
    __shared__ float zs[64];
    __shared__ int nlist_s[8];
    __shared__ int cnt_s;

    const int tid = threadIdx.x, lane = tid & 31, warp = tid >> 5;
    const int m0 = blockIdx.x * BM;
    const int o  = blockIdx.y;

    if (tid < 64) zs[tid] = gate_z(u_param, alpha, tid);
    __syncthreads();
    if (tid == 0) {
        int c = 0;
#pragma unroll
        for (int nn = 0; nn < 8; nn++)
            if (zs[o * 8 + nn] > 0.0f) nlist_s[c++] = nn;
        cnt_s = c;
    }
    __syncthreads();
    const int chunks = cnt_s * 4;     // 4 x BK=64 chunks per active n

    // ---- fast path: closed o -> coalesced write-through zeros ----
    if (chunks == 0) {
        float* base = out + ((size_t)m0 * O_ + o) * V_;
        const uint4 z4 = make_uint4(0u, 0u, 0u, 0u);
#pragma unroll
        for (int i = tid; i < 8192; i += 512) {       // 128 rows x 64 uint4
            int r = i >> 6, c = i & 63;
            __stwt(reinterpret_cast<uint4*>(base + (size_t)r * (O_ * V_)) + c, z4);
        }
        return;
    }

    const __half* Ag = g_xh + (size_t)m0 * K_;
    const __half* Bg = g_wh + (size_t)o * V_ * K_;

    // cp.async per stage: A 1024 ops (2/thread) + B 2048 ops (4/thread)
    auto issue = [&](int c) {
        const uint32_t so = (uint32_t)(c & 1) * STG_BYTES;
        const int k0 = (nlist_s[c >> 2] << 8) + ((c & 3) << 6);
#pragma unroll
        for (int i = 0; i < 2; i++) {
            int idx = tid + i * 512;
            int r = idx >> 3, cc = idx & 7;
            cpa16(sb + so + r * ROWB + cc * 16, Ag + (size_t)r * K_ + k0 + cc * 8);
        }
#pragma unroll
        for (int i = 0; i < 4; i++) {
            int idx = tid + i * 512;
            int r = idx >> 3, cc = idx & 7;
            cpa16(sb + so + A_BYTES + r * ROWB + cc * 16,
                  Bg + (size_t)r * K_ + k0 + cc * 8);
        }
    };

    const int mo = (warp >> 2) * 32;   // 4 warps in m
    const int no = (warp & 3) * 64;    // 4 warps in n
    uint32_t a_addr[2], b_addr[4];
    {
        const int arl = lane & 15;
        const int akh = (lane >> 4) & 1;
#pragma unroll
        for (int mf = 0; mf < 2; mf++)
            a_addr[mf] = sb + (mo + mf * 16 + arl) * ROWB + akh * 16;
        const int brl = (lane & 7) + ((lane >> 4) & 1) * 8;
        const int bkh = (lane >> 3) & 1;
#pragma unroll
        for (int p = 0; p < 4; p++)
            b_addr[p] = sb + A_BYTES + (no + p * 16 + brl) * ROWB + bkh * 16;
    }

    float acc[2][8][4];
#pragma unroll
    for (int i = 0; i < 2; i++)
#pragma unroll
        for (int j = 0; j < 8; j++)
#pragma unroll
            for (int k = 0; k < 4; k++) acc[i][j][k] = 0.0f;

    issue(0); CP_COMMIT();

    for (int c = 0; c < chunks; ++c) {
        if (c + 1 < chunks) issue(c + 1);
        CP_COMMIT();
        CP_WAIT1();               // group c complete (<=1 pending)
        __syncthreads();

        const uint32_t so = (uint32_t)(c & 1) * STG_BYTES;
#pragma unroll
        for (int ks = 0; ks < 4; ks++) {       // 4 k16 steps per BK=64
            const uint32_t kb = so + ks * 32;
            uint32_t a[2][4], b[4][4];
#pragma unroll
            for (int mf = 0; mf < 2; mf++) ldsm4(a[mf], a_addr[mf] + kb);
#pragma unroll
            for (int p = 0; p < 4; p++) ldsm4(b[p], b_addr[p] + kb);
#pragma unroll
            for (int mf = 0; mf < 2; mf++)
#pragma unroll
                for (int p = 0; p < 4; p++) {
                    mma16816(acc[mf][2 * p],     a[mf], b[p][0], b[p][1]);
                    mma16816(acc[mf][2 * p + 1], a[mf], b[p][2], b[p][3]);
                }
        }
        __syncthreads();          // stage c reused by issue(c+2) next iter
    }

    const int gid = lane >> 2, tig = lane & 3;
#pragma unroll
    for (int mf = 0; mf < 2; mf++) {
        const int brow = m0 + mo + mf * 16 + gid;
#pragma unroll
        for (int nb = 0; nb < 8; nb++) {
            const int v = no + nb * 8 + tig * 2;
            float* c = acc[mf][nb];
            __stwt(reinterpret_cast<float2*>(
                out + ((size_t)brow * O_ + o) * V_ + v), make_float2(c[0], c[1]));
            __stwt(reinterpret_cast<float2*>(
                out + ((size_t)(brow + 8) * O_ + o) * V_ + v), make_float2(c[2], c[3]));
        }
    }
}

// ===================== host =====================
extern "C" void kernel_launch(void* const* d_in, const int* in_sizes, int n_in,
                              void* d_out, int out_size) {
    const float* x = nullptr, *alpha = nullptr, *u = nullptr, *T = nullptr;
    for (int i = 0; i < n_in; i++) {
        switch (in_sizes[i]) {
            case 16777216: x     = (const float*)d_in[i]; break;
            case 1:        alpha = (const float*)d_in[i]; break;
            case 64:       u     = (const float*)d_in[i]; break;
            case 4194304:  T     = (const float*)d_in[i]; break;
        }
    }
    if (!x || !alpha || !u || !T) return;
    float* out = (float*)d_out;

    static bool attr_set = false;
    if (!attr_set) {
        cudaFuncSetAttribute(gemm_fp16, cudaFuncAttributeMaxDynamicSharedMemorySize,
                             SMEM_TOTAL);
        attr_set = true;
    }

    prep<<<3072, 256>>>(x, T, alpha, u);
    gemm_fp16<<<dim3(64, 8), 512, SMEM_TOTAL>>>(alpha, u, out);
}

// round 12
// speedup vs baseline: 1.0626x; 1.0626x over previous
#include <cuda_runtime.h>
#include <cuda.h>
#include <cuda_fp16.h>
#include <cstdint>

// ===================== problem constants =====================
#define BATCH_ 8192
#define O_     8
#define K_     2048      // N*U
#define V_     256

// ===================== GEMM tiling =====================
#define BM 128
#define BN 256           // full o per CTA
#define BK 64            // 64 halves = 128B per row per stage
#define NSTG 3
#define A_ST 16384       // 128 rows x 128B
#define B_ST 32768       // 256 rows x 128B
#define ST_BYTES (A_ST + B_ST)              // 49152
#define SMEM_ALLOC (NSTG * ST_BYTES + 1024) // + alignment slack

// ===================== scratch =====================
__device__ __half g_xh[(size_t)BATCH_ * K_];   // fp16 X (active n-slices only)
__device__ __half g_wh[(size_t)O_ * V_ * K_];  // gated, transposed fp16 W [o][v][k]

// ===================== helpers =====================
__device__ __forceinline__ uint32_t smem_u32(const void* p) {
    uint32_t a;
    asm("{ .reg .u64 t; cvta.to.shared.u64 t, %1; cvt.u32.u64 %0, t; }" : "=r"(a) : "l"(p));
    return a;
}
__device__ __forceinline__ void ldsm4(uint32_t (&r)[4], uint32_t addr) {
    asm volatile("ldmatrix.sync.aligned.m8n8.x4.shared.b16 {%0,%1,%2,%3}, [%4];"
                 : "=r"(r[0]), "=r"(r[1]), "=r"(r[2]), "=r"(r[3]) : "r"(addr));
}
__device__ __forceinline__ void mma16816(float* c, const uint32_t* a,
                                         uint32_t b0, uint32_t b1) {
    asm volatile(
        "mma.sync.aligned.m16n8k16.row.col.f32.f16.f16.f32 "
        "{%0,%1,%2,%3}, {%4,%5,%6,%7}, {%8,%9}, {%0,%1,%2,%3};"
        : "+f"(c[0]), "+f"(c[1]), "+f"(c[2]), "+f"(c[3])
        : "r"(a[0]), "r"(a[1]), "r"(a[2]), "r"(a[3]), "r"(b0), "r"(b1));
}
#define MBAR_INIT(a, n)   asm volatile("mbarrier.init.shared.b64 [%0], %1;" :: "r"(a), "r"(n) : "memory")
#define MBAR_EXPECT(a, b) asm volatile("mbarrier.arrive.expect_tx.shared.b64 _, [%0], %1;" :: "r"(a), "r"(b) : "memory")
__device__ __forceinline__ void mbar_wait(uint32_t addr, uint32_t phase) {
    asm volatile(
        "{\n\t.reg .pred P;\n"
        "WL_%=:\n\t"
        "mbarrier.try_wait.parity.acquire.cta.shared::cta.b64 P, [%0], %1, 0x989680;\n\t"
        "@P bra WD_%=;\n\t"
        "bra WL_%=;\n"
        "WD_%=:\n\t}"
        :: "r"(addr), "r"(phase) : "memory");
}
__device__ __forceinline__ void tma2d(uint32_t dst, const CUtensorMap* m,
                                      int x, int y, uint32_t bar) {
    asm volatile(
        "cp.async.bulk.tensor.2d.shared::cta.global.tile.mbarrier::complete_tx::bytes "
        "[%0], [%1, {%2, %3}], [%4];"
        :: "r"(dst), "l"(m), "r"(x), "r"(y), "r"(bar) : "memory");
}
__device__ __forceinline__ void tma3d(uint32_t dst, const CUtensorMap* m,
                                      int x, int y, int z, uint32_t bar) {
    asm volatile(
        "cp.async.bulk.tensor.3d.shared::cta.global.tile.mbarrier::complete_tx::bytes "
        "[%0], [%1, {%2, %3, %4}], [%5];"
        :: "r"(dst), "l"(m), "r"(x), "r"(y), "r"(z), "r"(bar) : "memory");
}

// fast-math gate (identical everywhere -> consistent open/closed decisions)
__device__ __forceinline__ float gate_z(const float* u_param, const float* alpha, int idx) {
    float uu = u_param[idx];
    float s = __logf(uu) - __logf(1.0f - uu) + __logf(alpha[0]) * (1.0f / 0.9f);
    s = 1.0f / (1.0f + __expf(-s));
    float z = s * 1.2f - 0.1f;
    return fminf(fmaxf(z, 0.0f), 1.0f);
}

// ===================== prepass (3072 blocks, 256 threads) =====================
__global__ void prep(const float* __restrict__ X,
                     const float* __restrict__ T,
                     const float* __restrict__ alpha,
                     const float* __restrict__ u_param) {
    __shared__ float zs[64];
    __shared__ int actn[8];
    int tid = threadIdx.x;
    if (tid < 64) zs[tid] = gate_z(u_param, alpha, tid);
    __syncthreads();

    if (blockIdx.x < 2048) {
        if (tid < 8) {
            int a = 0;
#pragma unroll
            for (int o = 0; o < 8; o++) a |= (zs[o * 8 + tid] > 0.0f);
            actn[tid] = a;
        }
        __syncthreads();
        int b  = (blockIdx.x << 2) + (tid >> 6);
        int u4 = tid & 63;
#pragma unroll
        for (int n = 0; n < 8; n++) {
            if (!actn[n]) continue;
            size_t e = ((size_t)b * 8 + n) * 256 + u4 * 4;
            float4 v = *reinterpret_cast<const float4*>(X + e);
            __half2 h0 = __floats2half2_rn(v.x, v.y);
            __half2 h1 = __floats2half2_rn(v.z, v.w);
            uint2 w;
            w.x = *reinterpret_cast<uint32_t*>(&h0);
            w.y = *reinterpret_cast<uint32_t*>(&h1);
            *reinterpret_cast<uint2*>(g_xh + e) = w;
        }
        return;
    }

    __shared__ float tile[64][65];
    int blk = blockIdx.x - 2048;   // 0..1023
    int on = blk >> 4;
    int o = on >> 3, n = on & 7;
    int u0 = ((blk >> 2) & 3) * 64;
    int v0 = (blk & 3) * 64;
    float z = zs[o * 8 + n];
    if (z == 0.0f) return;

    const float* tb = T + (((size_t)(o * 8 + n) * 256 + u0) * 256 + v0);
#pragma unroll
    for (int i = 0; i < 16; i++) {
        int r = i * 4 + (tid >> 6);
        int c = tid & 63;
        tile[r][c] = tb[(size_t)r * 256 + c];
    }
    __syncthreads();

    __half* wb = g_wh + ((size_t)o * 256 + v0) * 2048 + n * 256 + u0;
#pragma unroll
    for (int i = 0; i < 16; i++) {
        int r = i * 4 + (tid >> 6);
        int c = tid & 63;
        wb[(size_t)r * 2048 + c] = __float2half_rn(tile[c][r] * z);
    }
}

// ===================== TMA-fed fp16 GEMM =====================
// Tile BM=128 x BN=256 (full o). Grid (64, 8): x = m-tile, y = o.
// 512 threads = 16 warps (4m x 4n). 3-stage TMA pipeline, SW128 tiles.
__global__ __launch_bounds__(512)
void gemm_fp16(const __grid_constant__ CUtensorMap tma_a,
               const __grid_constant__ CUtensorMap tma_b,
               const float* __restrict__ alpha,
               const float* __restrict__ u_param,
               float* __restrict__ out) {
    extern __shared__ char smem[];
    __shared__ uint64_t bars[NSTG];
    __shared__ float zs[64];
    __shared__ int nlist_s[8];
    __shared__ int cnt_s;

    const int tid = threadIdx.x, lane = tid & 31, warp = tid >> 5;
    const int m0 = blockIdx.x * BM;
    const int o  = blockIdx.y;

    if (tid < 64) zs[tid] = gate_z(u_param, alpha, tid);
    __syncthreads();
    if (tid == 0) {
        int c = 0;
#pragma unroll
        for (int nn = 0; nn < 8; nn++)
            if (zs[o * 8 + nn] > 0.0f) nlist_s[c++] = nn;
        cnt_s = c;
    }
    __syncthreads();
    const int chunks = cnt_s * 4;     // 4 x BK=64 chunks per active n

    // ---- fast path: closed o -> coalesced write-through zeros ----
    if (chunks == 0) {
        float* base = out + ((size_t)m0 * O_ + o) * V_;
        const uint4 z4 = make_uint4(0u, 0u, 0u, 0u);
#pragma unroll
        for (int i = tid; i < 8192; i += 512) {       // 128 rows x 64 uint4
            int r = i >> 6, c = i & 63;
            __stwt(reinterpret_cast<uint4*>(base + (size_t)r * (O_ * V_)) + c, z4);
        }
        return;
    }

    const uint32_t DATA = (smem_u32(smem) + 1023u) & ~1023u;
    const uint32_t BARS = smem_u32(bars);

    if (tid == 0) {
#pragma unroll
        for (int s = 0; s < NSTG; s++) MBAR_INIT(BARS + 8 * s, 1);
    }
    __syncthreads();

    auto issue = [&](int c) {
        const int s = c % NSTG;
        const uint32_t dst = DATA + (uint32_t)s * ST_BYTES;
        const int k0 = (nlist_s[c >> 2] << 8) + ((c & 3) << 6);
        MBAR_EXPECT(BARS + 8 * s, ST_BYTES);
        tma2d(dst,        &tma_a, k0, m0, BARS + 8 * s);
        tma3d(dst + A_ST, &tma_b, k0, 0, o, BARS + 8 * s);
    };
    if (tid == 0) {
        issue(0);
        if (chunks > 1) issue(1);
        if (chunks > 2) issue(2);
    }

    // ldmatrix lane addressing with SW128 XOR: addr = base + row*128 + (col ^ ((row&7)<<4))
    const int mo = (warp >> 2) * 32;   // 4 warps in m
    const int no = (warp & 3) * 64;    // 4 warps in n
    uint32_t aoff[2], arx[2], boff[4], brx[4];
    const uint32_t akh16 = ((lane >> 4) & 1) * 16;
    const uint32_t bkh16 = ((lane >> 3) & 1) * 16;
    {
        const int arl = lane & 15;
#pragma unroll
        for (int mf = 0; mf < 2; mf++) {
            int row = mo + mf * 16 + arl;
            aoff[mf] = (uint32_t)row * 128;
            arx[mf]  = (uint32_t)(row & 7) << 4;
        }
        const int brl = (lane & 7) + ((lane >> 4) & 1) * 8;
#pragma unroll
        for (int p = 0; p < 4; p++) {
            int row = no + p * 16 + brl;
            boff[p] = (uint32_t)row * 128 + A_ST;
            brx[p]  = (uint32_t)(row & 7) << 4;
        }
    }

    float acc[2][8][4];
#pragma unroll
    for (int i = 0; i < 2; i++)
#pragma unroll
        for (int j = 0; j < 8; j++)
#pragma unroll
            for (int k = 0; k < 4; k++) acc[i][j][k] = 0.0f;

    for (int c = 0; c < chunks; ++c) {
        const int s = c % NSTG;
        mbar_wait(BARS + 8 * s, (c / NSTG) & 1);
        const uint32_t sbase = DATA + (uint32_t)s * ST_BYTES;

#pragma unroll
        for (int ks = 0; ks < 4; ks++) {       // 4 k16 steps per BK=64
            const uint32_t acol = (uint32_t)ks * 32 + akh16;
            const uint32_t bcol = (uint32_t)ks * 32 + bkh16;
            uint32_t a[2][4], b[4][4];
#pragma unroll
            for (int mf = 0; mf < 2; mf++)
                ldsm4(a[mf], sbase + aoff[mf] + (acol ^ arx[mf]));
#pragma unroll
            for (int p = 0; p < 4; p++)
                ldsm4(b[p], sbase + boff[p] + (bcol ^ brx[p]));
#pragma unroll
            for (int mf = 0; mf < 2; mf++)
#pragma unroll
                for (int p = 0; p < 4; p++) {
                    mma16816(acc[mf][2 * p],     a[mf], b[p][0], b[p][1]);
                    mma16816(acc[mf][2 * p + 1], a[mf], b[p][2], b[p][3]);
                }
        }
        __syncthreads();                       // all reads of stage s done
        if (tid == 0 && c + NSTG < chunks) issue(c + NSTG);
    }

    const int gid = lane >> 2, tig = lane & 3;
#pragma unroll
    for (int mf = 0; mf < 2; mf++) {
        const int brow = m0 + mo + mf * 16 + gid;
#pragma unroll
        for (int nb = 0; nb < 8; nb++) {
            const int v = no + nb * 8 + tig * 2;
            float* c = acc[mf][nb];
            __stwt(reinterpret_cast<float2*>(
                out + ((size_t)brow * O_ + o) * V_ + v), make_float2(c[0], c[1]));
            __stwt(reinterpret_cast<float2*>(
                out + ((size_t)(brow + 8) * O_ + o) * V_ + v), make_float2(c[2], c[3]));
        }
    }
}

// ===================== host =====================
typedef CUresult (*PFN_tmEncode)(CUtensorMap*, CUtensorMapDataType, cuuint32_t, void*,
                                 const cuuint64_t*, const cuuint64_t*, const cuuint32_t*,
                                 const cuuint32_t*, CUtensorMapInterleave, CUtensorMapSwizzle,
                                 CUtensorMapL2promotion, CUtensorMapFloatOOBfill);

extern "C" void kernel_launch(void* const* d_in, const int* in_sizes, int n_in,
                              void* d_out, int out_size) {
    const float* x = nullptr, *alpha = nullptr, *u = nullptr, *T = nullptr;
    for (int i = 0; i < n_in; i++) {
        switch (in_sizes[i]) {
            case 16777216: x     = (const float*)d_in[i]; break;
            case 1:        alpha = (const float*)d_in[i]; break;
            case 64:       u     = (const float*)d_in[i]; break;
            case 4194304:  T     = (const float*)d_in[i]; break;
        }
    }
    if (!x || !alpha || !u || !T) return;
    float* out = (float*)d_out;

    void* xh_ptr = nullptr; cudaGetSymbolAddress(&xh_ptr, g_xh);
    void* wh_ptr = nullptr; cudaGetSymbolAddress(&wh_ptr, g_wh);

    void* pfn = nullptr;
#if CUDART_VERSION >= 12050
    cudaDriverEntryPointQueryResult qr;
    cudaGetDriverEntryPointByVersion("cuTensorMapEncodeTiled", &pfn, 12000,
                                     cudaEnableDefault, &qr);
#else
    cudaGetDriverEntryPoint("cuTensorMapEncodeTiled", &pfn, cudaEnableDefault);
#endif
    PFN_tmEncode enc = (PFN_tmEncode)pfn;

    CUtensorMap ta{}, tb{};
    {   // A: g_xh [8192 rows x 2048 K] fp16, box 64(K) x 128(rows), SW128
        cuuint64_t dims[2]    = { (cuuint64_t)K_, (cuuint64_t)BATCH_ };
        cuuint64_t strides[1] = { (cuuint64_t)K_ * 2 };
        cuuint32_t box[2]     = { BK, BM };
        cuuint32_t es[2]      = { 1, 1 };
        enc(&ta, CU_TENSOR_MAP_DATA_TYPE_FLOAT16, 2, xh_ptr, dims, strides, box, es,
            CU_TENSOR_MAP_INTERLEAVE_NONE, CU_TENSOR_MAP_SWIZZLE_128B,
            CU_TENSOR_MAP_L2_PROMOTION_L2_128B, CU_TENSOR_MAP_FLOAT_OOB_FILL_NONE);
    }
    {   // B: g_wh [8 o x 256 v x 2048 K] fp16, box 64(K) x 256(v) x 1, SW128
        cuuint64_t dims[3]    = { (cuuint64_t)K_, (cuuint64_t)V_, (cuuint64_t)O_ };
        cuuint64_t strides[2] = { (cuuint64_t)K_ * 2, (cuuint64_t)K_ * V_ * 2 };
        cuuint32_t box[3]     = { BK, BN, 1 };
        cuuint32_t es[3]      = { 1, 1, 1 };
        enc(&tb, CU_TENSOR_MAP_DATA_TYPE_FLOAT16, 3, wh_ptr, dims, strides, box, es,
            CU_TENSOR_MAP_INTERLEAVE_NONE, CU_TENSOR_MAP_SWIZZLE_128B,
            CU_TENSOR_MAP_L2_PROMOTION_L2_128B, CU_TENSOR_MAP_FLOAT_OOB_FILL_NONE);
    }

    static bool attr_set = false;
    if (!attr_set) {
        cudaFuncSetAttribute(gemm_fp16, cudaFuncAttributeMaxDynamicSharedMemorySize,
                             SMEM_ALLOC);
        attr_set = true;
    }

    prep<<<3072, 256>>>(x, T, alpha, u);
    gemm_fp16<<<dim3(64, 8), 512, SMEM_ALLOC>>>(ta, tb, alpha, u, out);
}

// round 13
// speedup vs baseline: 1.2105x; 1.1393x over previous
#include <cuda_runtime.h>
#include <cuda.h>
#include <cuda_fp16.h>
#include <cstdint>

// ===================== problem constants =====================
#define BATCH_ 8192
#define O_     8
#define K_     2048      // N*U
#define V_     256

// ===================== GEMM tiling =====================
#define BM 64
#define BN 256           // full o per CTA
#define BK 64            // 64 halves = 128B per row per stage
#define NSTG 2
#define A_ST 8192        // 64 rows x 128B
#define B_ST 32768       // 256 rows x 128B
#define ST_BYTES (A_ST + B_ST)              // 40960
#define SMEM_ALLOC (NSTG * ST_BYTES + 1024) // 82944 -> 2 CTAs/SM

// ===================== scratch =====================
__device__ __half g_xh[(size_t)BATCH_ * K_];   // fp16 X (active n-slices only)
__device__ __half g_wh[(size_t)O_ * V_ * K_];  // gated, transposed fp16 W [o][v][k]

// ===================== helpers =====================
__device__ __forceinline__ uint32_t smem_u32(const void* p) {
    uint32_t a;
    asm("{ .reg .u64 t; cvta.to.shared.u64 t, %1; cvt.u32.u64 %0, t; }" : "=r"(a) : "l"(p));
    return a;
}
__device__ __forceinline__ void ldsm4(uint32_t (&r)[4], uint32_t addr) {
    asm volatile("ldmatrix.sync.aligned.m8n8.x4.shared.b16 {%0,%1,%2,%3}, [%4];"
                 : "=r"(r[0]), "=r"(r[1]), "=r"(r[2]), "=r"(r[3]) : "r"(addr));
}
__device__ __forceinline__ void mma16816(float* c, const uint32_t* a,
                                         uint32_t b0, uint32_t b1) {
    asm volatile(
        "mma.sync.aligned.m16n8k16.row.col.f32.f16.f16.f32 "
        "{%0,%1,%2,%3}, {%4,%5,%6,%7}, {%8,%9}, {%0,%1,%2,%3};"
        : "+f"(c[0]), "+f"(c[1]), "+f"(c[2]), "+f"(c[3])
        : "r"(a[0]), "r"(a[1]), "r"(a[2]), "r"(a[3]), "r"(b0), "r"(b1));
}
#define MBAR_INIT(a, n)   asm volatile("mbarrier.init.shared.b64 [%0], %1;" :: "r"(a), "r"(n) : "memory")
#define MBAR_EXPECT(a, b) asm volatile("mbarrier.arrive.expect_tx.shared.b64 _, [%0], %1;" :: "r"(a), "r"(b) : "memory")
__device__ __forceinline__ void mbar_wait(uint32_t addr, uint32_t phase) {
    asm volatile(
        "{\n\t.reg .pred P;\n"
        "WL_%=:\n\t"
        "mbarrier.try_wait.parity.acquire.cta.shared::cta.b64 P, [%0], %1, 0x989680;\n\t"
        "@P bra WD_%=;\n\t"
        "bra WL_%=;\n"
        "WD_%=:\n\t}"
        :: "r"(addr), "r"(phase) : "memory");
}
__device__ __forceinline__ void tma2d(uint32_t dst, const CUtensorMap* m,
                                      int x, int y, uint32_t bar) {
    asm volatile(
        "cp.async.bulk.tensor.2d.shared::cta.global.tile.mbarrier::complete_tx::bytes "
        "[%0], [%1, {%2, %3}], [%4];"
        :: "r"(dst), "l"(m), "r"(x), "r"(y), "r"(bar) : "memory");
}
__device__ __forceinline__ void tma3d(uint32_t dst, const CUtensorMap* m,
                                      int x, int y, int z, uint32_t bar) {
    asm volatile(
        "cp.async.bulk.tensor.3d.shared::cta.global.tile.mbarrier::complete_tx::bytes "
        "[%0], [%1, {%2, %3, %4}], [%5];"
        :: "r"(dst), "l"(m), "r"(x), "r"(y), "r"(z), "r"(bar) : "memory");
}

// fast-math gate (identical everywhere -> consistent open/closed decisions)
__device__ __forceinline__ float gate_z(const float* u_param, const float* alpha, int idx) {
    float uu = u_param[idx];
    float s = __logf(uu) - __logf(1.0f - uu) + __logf(alpha[0]) * (1.0f / 0.9f);
    s = 1.0f / (1.0f + __expf(-s));
    float z = s * 1.2f - 0.1f;
    return fminf(fmaxf(z, 0.0f), 1.0f);
}

// ===================== prepass (3072 blocks, 256 threads) =====================
__global__ void prep(const float* __restrict__ X,
                     const float* __restrict__ T,
                     const float* __restrict__ alpha,
                     const float* __restrict__ u_param) {
    __shared__ float zs[64];
    __shared__ int actn[8];
    int tid = threadIdx.x;
    if (tid < 64) zs[tid] = gate_z(u_param, alpha, tid);
    __syncthreads();

    if (blockIdx.x < 2048) {
        if (tid < 8) {
            int a = 0;
#pragma unroll
            for (int o = 0; o < 8; o++) a |= (zs[o * 8 + tid] > 0.0f);
            actn[tid] = a;
        }
        __syncthreads();
        int b  = (blockIdx.x << 2) + (tid >> 6);
        int u4 = tid & 63;
#pragma unroll
        for (int n = 0; n < 8; n++) {
            if (!actn[n]) continue;
            size_t e = ((size_t)b * 8 + n) * 256 + u4 * 4;
            float4 v = *reinterpret_cast<const float4*>(X + e);
            __half2 h0 = __floats2half2_rn(v.x, v.y);
            __half2 h1 = __floats2half2_rn(v.z, v.w);
            uint2 w;
            w.x = *reinterpret_cast<uint32_t*>(&h0);
            w.y = *reinterpret_cast<uint32_t*>(&h1);
            *reinterpret_cast<uint2*>(g_xh + e) = w;
        }
        return;
    }

    __shared__ float tile[64][65];
    int blk = blockIdx.x - 2048;   // 0..1023
    int on = blk >> 4;
    int o = on >> 3, n = on & 7;
    int u0 = ((blk >> 2) & 3) * 64;
    int v0 = (blk & 3) * 64;
    float z = zs[o * 8 + n];
    if (z == 0.0f) return;

    const float* tb = T + (((size_t)(o * 8 + n) * 256 + u0) * 256 + v0);
#pragma unroll
    for (int i = 0; i < 16; i++) {
        int r = i * 4 + (tid >> 6);
        int c = tid & 63;
        tile[r][c] = tb[(size_t)r * 256 + c];
    }
    __syncthreads();

    __half* wb = g_wh + ((size_t)o * 256 + v0) * 2048 + n * 256 + u0;
#pragma unroll
    for (int i = 0; i < 16; i++) {
        int r = i * 4 + (tid >> 6);
        int c = tid & 63;
        wb[(size_t)r * 2048 + c] = __float2half_rn(tile[c][r] * z);
    }
}

// ===================== TMA-fed fp16 GEMM =====================
// Tile BM=64 x BN=256 (full o). Grid (128, 8): x = m-tile (fast), y = o.
// 256 threads = 8 warps (2m x 4n), warp tile 32x64. 2-stage TMA pipeline.
__global__ __launch_bounds__(256)
void gemm_fp16(const __grid_constant__ CUtensorMap tma_a,
               const __grid_constant__ CUtensorMap tma_b,
               const float* __restrict__ alpha,
               const float* __restrict__ u_param,
               float* __restrict__ out) {
    extern __shared__ char smem[];
    __shared__ uint64_t bars[NSTG];
    __shared__ float zs[64];
    __shared__ int nlist_s[8];
    __shared__ int cnt_s;

    const int tid = threadIdx.x, lane = tid & 31, warp = tid >> 5;
    const int m0 = blockIdx.x * BM;
    const int o  = blockIdx.y;

    if (tid < 64) zs[tid] = gate_z(u_param, alpha, tid);
    __syncthreads();
    if (tid == 0) {
        int c = 0;
#pragma unroll
        for (int nn = 0; nn < 8; nn++)
            if (zs[o * 8 + nn] > 0.0f) nlist_s[c++] = nn;
        cnt_s = c;
    }
    __syncthreads();
    const int chunks = cnt_s * 4;     // 4 x BK=64 chunks per active n

    // ---- fast path: closed o -> coalesced write-through zeros ----
    if (chunks == 0) {
        float* base = out + ((size_t)m0 * O_ + o) * V_;
        const uint4 z4 = make_uint4(0u, 0u, 0u, 0u);
#pragma unroll
        for (int i = tid; i < 4096; i += 256) {       // 64 rows x 64 uint4
            int r = i >> 6, c = i & 63;
            __stwt(reinterpret_cast<uint4*>(base + (size_t)r * (O_ * V_)) + c, z4);
        }
        return;
    }

    const uint32_t DATA = (smem_u32(smem) + 1023u) & ~1023u;
    const uint32_t BARS = smem_u32(bars);

    if (tid == 0) {
#pragma unroll
        for (int s = 0; s < NSTG; s++) MBAR_INIT(BARS + 8 * s, 1);
    }
    __syncthreads();

    auto issue = [&](int c) {
        const int s = c & 1;
        const uint32_t dst = DATA + (uint32_t)s * ST_BYTES;
        const int k0 = (nlist_s[c >> 2] << 8) + ((c & 3) << 6);
        MBAR_EXPECT(BARS + 8 * s, ST_BYTES);
        tma2d(dst,        &tma_a, k0, m0, BARS + 8 * s);
        tma3d(dst + A_ST, &tma_b, k0, 0, o, BARS + 8 * s);
    };
    if (tid == 0) {
        issue(0);
        if (chunks > 1) issue(1);
    }

    // ldmatrix lane addressing with SW128 XOR: addr = base + row*128 + (col ^ ((row&7)<<4))
    const int mo = (warp >> 2) * 32;   // 2 warps in m
    const int no = (warp & 3) * 64;    // 4 warps in n
    uint32_t aoff[2], arx[2], boff[4], brx[4];
    const uint32_t akh16 = ((lane >> 4) & 1) * 16;
    const uint32_t bkh16 = ((lane >> 3) & 1) * 16;
    {
        const int arl = lane & 15;
#pragma unroll
        for (int mf = 0; mf < 2; mf++) {
            int row = mo + mf * 16 + arl;
            aoff[mf] = (uint32_t)row * 128;
            arx[mf]  = (uint32_t)(row & 7) << 4;
        }
        const int brl = (lane & 7) + ((lane >> 4) & 1) * 8;
#pragma unroll
        for (int p = 0; p < 4; p++) {
            int row = no + p * 16 + brl;
            boff[p] = (uint32_t)row * 128 + A_ST;
            brx[p]  = (uint32_t)(row & 7) << 4;
        }
    }

    float acc[2][8][4];
#pragma unroll
    for (int i = 0; i < 2; i++)
#pragma unroll
        for (int j = 0; j < 8; j++)
#pragma unroll
            for (int k = 0; k < 4; k++) acc[i][j][k] = 0.0f;

    for (int c = 0; c < chunks; ++c) {
        const int s = c & 1;
        mbar_wait(BARS + 8 * s, (c >> 1) & 1);
        const uint32_t sbase = DATA + (uint32_t)s * ST_BYTES;

#pragma unroll
        for (int ks = 0; ks < 4; ks++) {       // 4 k16 steps per BK=64
            const uint32_t acol = (uint32_t)ks * 32 + akh16;
            const uint32_t bcol = (uint32_t)ks * 32 + bkh16;
            uint32_t a[2][4], b[4][4];
#pragma unroll
            for (int mf = 0; mf < 2; mf++)
                ldsm4(a[mf], sbase + aoff[mf] + (acol ^ arx[mf]));
#pragma unroll
            for (int p = 0; p < 4; p++)
                ldsm4(b[p], sbase + boff[p] + (bcol ^ brx[p]));
#pragma unroll
            for (int mf = 0; mf < 2; mf++)
#pragma unroll
                for (int p = 0; p < 4; p++) {
                    mma16816(acc[mf][2 * p],     a[mf], b[p][0], b[p][1]);
                    mma16816(acc[mf][2 * p + 1], a[mf], b[p][2], b[p][3]);
                }
        }
        __syncthreads();                       // all reads of stage s done
        if (tid == 0 && c + NSTG < chunks) issue(c + NSTG);
    }

    const int gid = lane >> 2, tig = lane & 3;
#pragma unroll
    for (int mf = 0; mf < 2; mf++) {
        const int brow = m0 + mo + mf * 16 + gid;
#pragma unroll
        for (int nb = 0; nb < 8; nb++) {
            const int v = no + nb * 8 + tig * 2;
            float* c = acc[mf][nb];
            __stwt(reinterpret_cast<float2*>(
                out + ((size_t)brow * O_ + o) * V_ + v), make_float2(c[0], c[1]));
            __stwt(reinterpret_cast<float2*>(
                out + ((size_t)(brow + 8) * O_ + o) * V_ + v), make_float2(c[2], c[3]));
        }
    }
}

// ===================== host =====================
typedef CUresult (*PFN_tmEncode)(CUtensorMap*, CUtensorMapDataType, cuuint32_t, void*,
                                 const cuuint64_t*, const cuuint64_t*, const cuuint32_t*,
                                 const cuuint32_t*, CUtensorMapInterleave, CUtensorMapSwizzle,
                                 CUtensorMapL2promotion, CUtensorMapFloatOOBfill);

extern "C" void kernel_launch(void* const* d_in, const int* in_sizes, int n_in,
                              void* d_out, int out_size) {
    const float* x = nullptr, *alpha = nullptr, *u = nullptr, *T = nullptr;
    for (int i = 0; i < n_in; i++) {
        switch (in_sizes[i]) {
            case 16777216: x     = (const float*)d_in[i]; break;
            case 1:        alpha = (const float*)d_in[i]; break;
            case 64:       u     = (const float*)d_in[i]; break;
            case 4194304:  T     = (const float*)d_in[i]; break;
        }
    }
    if (!x || !alpha || !u || !T) return;
    float* out = (float*)d_out;

    void* xh_ptr = nullptr; cudaGetSymbolAddress(&xh_ptr, g_xh);
    void* wh_ptr = nullptr; cudaGetSymbolAddress(&wh_ptr, g_wh);

    void* pfn = nullptr;
#if CUDART_VERSION >= 12050
    cudaDriverEntryPointQueryResult qr;
    cudaGetDriverEntryPointByVersion("cuTensorMapEncodeTiled", &pfn, 12000,
                                     cudaEnableDefault, &qr);
#else
    cudaGetDriverEntryPoint("cuTensorMapEncodeTiled", &pfn, cudaEnableDefault);
#endif
    PFN_tmEncode enc = (PFN_tmEncode)pfn;

    CUtensorMap ta{}, tb{};
    {   // A: g_xh [8192 rows x 2048 K] fp16, box 64(K) x 64(rows), SW128
        cuuint64_t dims[2]    = { (cuuint64_t)K_, (cuuint64_t)BATCH_ };
        cuuint64_t strides[1] = { (cuuint64_t)K_ * 2 };
        cuuint32_t box[2]     = { BK, BM };
        cuuint32_t es[2]      = { 1, 1 };
        enc(&ta, CU_TENSOR_MAP_DATA_TYPE_FLOAT16, 2, xh_ptr, dims, strides, box, es,
            CU_TENSOR_MAP_INTERLEAVE_NONE, CU_TENSOR_MAP_SWIZZLE_128B,
            CU_TENSOR_MAP_L2_PROMOTION_L2_128B, CU_TENSOR_MAP_FLOAT_OOB_FILL_NONE);
    }
    {   // B: g_wh [8 o x 256 v x 2048 K] fp16, box 64(K) x 256(v) x 1, SW128
        cuuint64_t dims[3]    = { (cuuint64_t)K_, (cuuint64_t)V_, (cuuint64_t)O_ };
        cuuint64_t strides[2] = { (cuuint64_t)K_ * 2, (cuuint64_t)K_ * V_ * 2 };
        cuuint32_t box[3]     = { BK, BN, 1 };
        cuuint32_t es[3]      = { 1, 1, 1 };
        enc(&tb, CU_TENSOR_MAP_DATA_TYPE_FLOAT16, 3, wh_ptr, dims, strides, box, es,
            CU_TENSOR_MAP_INTERLEAVE_NONE, CU_TENSOR_MAP_SWIZZLE_128B,
            CU_TENSOR_MAP_L2_PROMOTION_L2_128B, CU_TENSOR_MAP_FLOAT_OOB_FILL_NONE);
    }

    static bool attr_set = false;
    if (!attr_set) {
        cudaFuncSetAttribute(gemm_fp16, cudaFuncAttributeMaxDynamicSharedMemorySize,
                             SMEM_ALLOC);
        attr_set = true;
    }

    prep<<<3072, 256>>>(x, T, alpha, u);
    gemm_fp16<<<dim3(128, 8), 256, SMEM_ALLOC>>>(ta, tb, alpha, u, out);
}